// round 11
// baseline (speedup 1.0000x reference)
#include <cuda_runtime.h>
#include <stdint.h>

// Problem constants (from reference):
//   NNZ = 819200, NUM_IDS = 16384, ITEMS_NUM = 100000, DIM = 128
// Inputs (metadata order): row_idx(int32, sorted), col_idx(int32),
//   data_tensor(f32), num_ids(scalar), embeddings(f32 [ITEMS,128])
// Output: f32 [num_ids, 128]

#define DIM 128
#define MAX_NUM_IDS 16384

// Scratch: CSR row offsets (allocation-free rule -> __device__ global).
__device__ int g_offsets[MAX_NUM_IDS + 1];

// Kernel 1: build row offsets from sorted row_idx.
// offsets[r] = first i with row_idx[i] >= r ; offsets[num_ids] = nnz.
__global__ void build_offsets_kernel(const int* __restrict__ row,
                                     int nnz, int num_ids) {
    int i = blockIdx.x * blockDim.x + threadIdx.x;
    if (i >= nnz) return;
    int r  = row[i];
    int rp = (i == 0) ? -1 : row[i - 1];
    // fill all segment starts in gap (rp, r]
    for (int q = rp + 1; q <= r; ++q) g_offsets[q] = i;
    if (i == nnz - 1) {
        for (int q = r + 1; q <= num_ids; ++q) g_offsets[q] = nnz;
    }
}

// Kernel 2: one warp per output row. Lane l owns dims [4l, 4l+4) (float4).
// Cols/weights staged 32-at-a-time in registers, broadcast via shfl.
// One LDG.128 per warp per nnz (512B fully coalesced), zero atomics.
__global__ void __launch_bounds__(256)
spmm_warp_per_row_kernel(const int*   __restrict__ col,
                         const float* __restrict__ w,
                         const float* __restrict__ emb,
                         float*       __restrict__ out,
                         int num_ids) {
    int gwarp = (blockIdx.x * blockDim.x + threadIdx.x) >> 5;
    if (gwarp >= num_ids) return;
    int lane = threadIdx.x & 31;

    int start = g_offsets[gwarp];
    int end   = g_offsets[gwarp + 1];

    float4 acc = make_float4(0.f, 0.f, 0.f, 0.f);

    for (int base = start; base < end; base += 32) {
        int n = end - base;
        if (n > 32) n = 32;
        int   c  = 0;
        float wt = 0.f;
        if (lane < n) {
            c  = col[base + lane];
            wt = w[base + lane];
        }
        #pragma unroll 4
        for (int j = 0; j < n; ++j) {
            int   cj = __shfl_sync(0xffffffffu, c,  j);
            float wj = __shfl_sync(0xffffffffu, wt, j);
            const float4 v = __ldg(reinterpret_cast<const float4*>(
                emb + (size_t)cj * DIM) + lane);
            acc.x = fmaf(wj, v.x, acc.x);
            acc.y = fmaf(wj, v.y, acc.y);
            acc.z = fmaf(wj, v.z, acc.z);
            acc.w = fmaf(wj, v.w, acc.w);
        }
    }

    reinterpret_cast<float4*>(out + (size_t)gwarp * DIM)[lane] = acc;
}

extern "C" void kernel_launch(void* const* d_in, const int* in_sizes, int n_in,
                              void* d_out, int out_size) {
    const int*   row = (const int*)  d_in[0];
    const int*   col = (const int*)  d_in[1];
    const float* dat = (const float*)d_in[2];
    // d_in[3] = num_ids scalar (unused; derive from out_size)
    const float* emb = (const float*)d_in[4];
    float*       out = (float*)d_out;

    const int nnz     = in_sizes[0];
    const int num_ids = out_size / DIM;   // 16384

    {
        int threads = 256;
        int blocks  = (nnz + threads - 1) / threads;
        build_offsets_kernel<<<blocks, threads>>>(row, nnz, num_ids);
    }
    {
        int threads = 256;                 // 8 warps -> 8 rows per block
        int total_warps = num_ids;
        int blocks = (total_warps * 32 + threads - 1) / threads;
        spmm_warp_per_row_kernel<<<blocks, threads>>>(col, dat, emb, out, num_ids);
    }
}

// round 12
// speedup vs baseline: 1.0077x; 1.0077x over previous
#include <cuda_runtime.h>
#include <stdint.h>

// Problem constants (from reference):
//   NNZ = 819200, NUM_IDS = 16384, ITEMS_NUM = 100000, DIM = 128
// Inputs (metadata order): row_idx(int32, sorted), col_idx(int32),
//   data_tensor(f32), num_ids(scalar), embeddings(f32 [ITEMS,128])
// Output: f32 [num_ids, 128]

#define DIM 128
#define MAX_NUM_IDS 16384

// Scratch: CSR row offsets (allocation-free rule -> __device__ global).
__device__ int g_offsets[MAX_NUM_IDS + 1];

// Kernel 1: build row offsets from sorted row_idx.
// offsets[r] = first i with row_idx[i] >= r ; offsets[num_ids] = nnz.
__global__ void build_offsets_kernel(const int* __restrict__ row,
                                     int nnz, int num_ids) {
    int i = blockIdx.x * blockDim.x + threadIdx.x;
    if (i >= nnz) return;
    int r  = row[i];
    int rp = (i == 0) ? -1 : row[i - 1];
    // fill all segment starts in gap (rp, r]
    for (int q = rp + 1; q <= r; ++q) g_offsets[q] = i;
    if (i == nnz - 1) {
        for (int q = r + 1; q <= num_ids; ++q) g_offsets[q] = nnz;
    }
}

// Kernel 2: one warp per output row. Lane l owns dims [4l, 4l+4) (float4).
// Cols/weights staged 32-at-a-time in registers, broadcast via shfl.
// One LDG.128 per warp per nnz (512B fully coalesced), zero atomics.
__global__ void __launch_bounds__(256)
spmm_warp_per_row_kernel(const int*   __restrict__ col,
                         const float* __restrict__ w,
                         const float* __restrict__ emb,
                         float*       __restrict__ out,
                         int num_ids) {
    int gwarp = (blockIdx.x * blockDim.x + threadIdx.x) >> 5;
    if (gwarp >= num_ids) return;
    int lane = threadIdx.x & 31;

    int start = g_offsets[gwarp];
    int end   = g_offsets[gwarp + 1];

    float4 acc = make_float4(0.f, 0.f, 0.f, 0.f);

    for (int base = start; base < end; base += 32) {
        int n = end - base;
        if (n > 32) n = 32;
        int   c  = 0;
        float wt = 0.f;
        if (lane < n) {
            c  = col[base + lane];
            wt = w[base + lane];
        }
        #pragma unroll 4
        for (int j = 0; j < n; ++j) {
            int   cj = __shfl_sync(0xffffffffu, c,  j);
            float wj = __shfl_sync(0xffffffffu, wt, j);
            const float4 v = __ldg(reinterpret_cast<const float4*>(
                emb + (size_t)cj * DIM) + lane);
            acc.x = fmaf(wj, v.x, acc.x);
            acc.y = fmaf(wj, v.y, acc.y);
            acc.z = fmaf(wj, v.z, acc.z);
            acc.w = fmaf(wj, v.w, acc.w);
        }
    }

    reinterpret_cast<float4*>(out + (size_t)gwarp * DIM)[lane] = acc;
}

extern "C" void kernel_launch(void* const* d_in, const int* in_sizes, int n_in,
                              void* d_out, int out_size) {
    const int*   row = (const int*)  d_in[0];
    const int*   col = (const int*)  d_in[1];
    const float* dat = (const float*)d_in[2];
    // d_in[3] = num_ids scalar (unused; derive from out_size)
    const float* emb = (const float*)d_in[4];
    float*       out = (float*)d_out;

    const int nnz     = in_sizes[0];
    const int num_ids = out_size / DIM;   // 16384

    {
        int threads = 256;
        int blocks  = (nnz + threads - 1) / threads;
        build_offsets_kernel<<<blocks, threads>>>(row, nnz, num_ids);
    }
    {
        int threads = 256;                 // 8 warps -> 8 rows per block
        int total_warps = num_ids;
        int blocks = (total_warps * 32 + threads - 1) / threads;
        spmm_warp_per_row_kernel<<<blocks, threads>>>(col, dat, emb, out, num_ids);
    }
}